// round 15
// baseline (speedup 1.0000x reference)
#include <cuda_runtime.h>
#include <cuda_bf16.h>
#include <cstdint>

#define N_NODES 100000
#define N_PAD 100096          // 391 * 256
#define N_EDGES 1600000
#define NLAYER 3
#define BN_EPS 1e-5f
#define SCAN_B 1024
#define CSR_GRID 98
#define RS_GRID 391
#define DONE_FLAG (-12345)

// -------- scratch (static device globals; allocation-free) --------
__device__ float g_H[(size_t)N_PAD * 256];
__device__ float g_T1[(size_t)N_PAD * 64];
__device__ float g_T2[(size_t)N_PAD * 64];
__device__ float g_AG[(size_t)N_PAD * 64];
__device__ float g_stats[11 * 128];
__device__ float g_scale[NLAYER * 128];
__device__ int g_sync[16];
__device__ __nv_bfloat16 g_Whi[11 * 4096];
__device__ __nv_bfloat16 g_Wlo[11 * 4096];
__device__ int g_cnt[N_NODES];
__device__ int g_excl[N_NODES];
__device__ int g_rowptr[N_NODES + 1];
__device__ int g_cursor[N_NODES];
__device__ int g_srcs[N_EDGES];
__device__ int g_bsum[CSR_GRID];

__device__ __forceinline__ uint32_t s2u(const void* p) {
    uint32_t a;
    asm("{ .reg .u64 t; cvta.to.shared.u64 t, %1; cvt.u32.u64 %0, t; }" : "=r"(a) : "l"(p));
    return a;
}
static __device__ __forceinline__ uint32_t swz(uint32_t off) { return off ^ ((off >> 3) & 0x70); }

#define LDSM_X4(r0, r1, r2, r3, addr)                                                          \
    asm volatile("ldmatrix.sync.aligned.m8n8.x4.shared.b16 {%0,%1,%2,%3}, [%4];"               \
                 : "=r"(r0), "=r"(r1), "=r"(r2), "=r"(r3)                                      \
                 : "r"(addr))
#define MMA(dst, a0, a1, a2, a3, b0, b1)                                                       \
    asm volatile(                                                                              \
        "mma.sync.aligned.m16n8k16.row.col.f32.bf16.bf16.f32 "                                 \
        "{%0,%1,%2,%3},{%4,%5,%6,%7},{%8,%9},{%0,%1,%2,%3};"                                   \
        : "+f"((dst)[0]), "+f"((dst)[1]), "+f"((dst)[2]), "+f"((dst)[3])                       \
        : "r"(a0), "r"(a1), "r"(a2), "r"(a3), "r"(b0), "r"(b1))

// ----------------- init: zero scratch + sync counters + weight transpose/split ----------
__global__ void k_init(float* stats, int* cnt, float* T1, float* T2, float* AG, float* H,
                       int* sync, const float* __restrict__ W_in, const float* __restrict__ W1,
                       const float* __restrict__ W2, const float* __restrict__ W_out1,
                       __nv_bfloat16* __restrict__ hi, __nv_bfloat16* __restrict__ lo) {
    int i = blockIdx.x * 256 + threadIdx.x;
    if (i < 11 * 128) stats[i] = 0.f;
    if (i < 16) sync[i] = 0;
    if (i < N_NODES) cnt[i] = 0;
    if (i < (N_PAD - N_NODES) * 64) {
        T1[(size_t)N_NODES * 64 + i] = 0.f;
        T2[(size_t)N_NODES * 64 + i] = 0.f;
        AG[(size_t)N_NODES * 64 + i] = 0.f;
    }
    if (i < (N_PAD - N_NODES) * 256) H[(size_t)N_NODES * 256 + i] = 0.f;
    if (i < 11 * 4096) {
        int slot = i >> 12, within = i & 4095;
        int n = within >> 6, k = within & 63;
        float v;
        if (slot == 0) v = W_in[k * 64 + n];
        else if (slot <= 3) v = W1[(slot - 1) * 4096 + k * 64 + n];
        else if (slot <= 6) v = W2[(slot - 4) * 4096 + k * 64 + n];
        else v = W_out1[((slot - 7) * 64 + k) * 64 + n];
        __nv_bfloat16 h = __float2bfloat16(v);
        hi[i] = h;
        lo[i] = __float2bfloat16(v - __bfloat162float(h));
    }
}

// ----------------- CSR build -----------------
__global__ void k_hist(const int* __restrict__ ei, int* __restrict__ cnt) {
    int e = blockIdx.x * 256 + threadIdx.x;
    atomicAdd(&cnt[ei[N_EDGES + e]], 1);
}
__global__ __launch_bounds__(SCAN_B) void k_scan1m(const int* __restrict__ cnt,
                                                   int* __restrict__ excl,
                                                   int* __restrict__ bsum,
                                                   int* __restrict__ ctr) {
    __shared__ int sm[SCAN_B];
    __shared__ int isLast;
    int tid = threadIdx.x;
    int i = blockIdx.x * SCAN_B + tid;
    int v = (i < N_NODES) ? cnt[i] : 0;
    sm[tid] = v;
    __syncthreads();
    for (int ofs = 1; ofs < SCAN_B; ofs <<= 1) {
        int t = (tid >= ofs) ? sm[tid - ofs] : 0;
        __syncthreads();
        sm[tid] += t;
        __syncthreads();
    }
    if (i < N_NODES) excl[i] = sm[tid] - v;
    if (tid == SCAN_B - 1) bsum[blockIdx.x] = sm[tid];
    __threadfence();
    __syncthreads();
    if (tid == 0) {
        int old = atomicAdd(ctr, 1);
        isLast = (old == CSR_GRID - 1);
    }
    __syncthreads();
    if (!isLast) return;
    int bv = (tid < CSR_GRID) ? bsum[tid] : 0;
    sm[tid] = bv;
    __syncthreads();
    for (int ofs = 1; ofs < 128; ofs <<= 1) {
        int t = (tid >= ofs && tid < 128) ? sm[tid - ofs] : 0;
        __syncthreads();
        if (tid < 128) sm[tid] += t;
        __syncthreads();
    }
    if (tid < CSR_GRID) bsum[tid] = sm[tid] - bv;
}
__global__ void k_scan3(const int* __restrict__ excl, const int* __restrict__ bsum,
                        int* __restrict__ rowptr, int* __restrict__ cursor) {
    int i = blockIdx.x * SCAN_B + threadIdx.x;
    if (i < N_NODES) {
        int r = excl[i] + bsum[blockIdx.x];
        rowptr[i] = r;
        cursor[i] = r;
    }
    if (i == 0) rowptr[N_NODES] = N_EDGES;
}
__global__ void k_fill(const int* __restrict__ ei, int* __restrict__ cursor,
                       int* __restrict__ srcs) {
    int e = blockIdx.x * 256 + threadIdx.x;
    int pos = atomicAdd(&cursor[ei[N_EDGES + e]], 1);
    srcs[pos] = ei[e];
}

// ----------------- CSR aggregation (max-parallel, 4-wide unrolled gather) -----------------
__global__ void k_aggr(const int* __restrict__ rowptr, const int* __restrict__ srcs,
                       const float* __restrict__ H, int off, const float* __restrict__ eps,
                       int li, float* __restrict__ AG) {
    int g = blockIdx.x * 256 + threadIdx.x;
    int node = g >> 4, lane = g & 15;
    float e = 1.f + eps[li];
    float4 self = *(const float4*)&H[(size_t)node * 256 + off + lane * 4];
    float4 a0 = make_float4(e * self.x, e * self.y, e * self.z, e * self.w);
    float4 a1 = make_float4(0.f, 0.f, 0.f, 0.f);
    int beg = rowptr[node], end = rowptr[node + 1];
    int j = beg;
    for (; j + 4 <= end; j += 4) {
        int s0 = __ldg(&srcs[j]);
        int s1 = __ldg(&srcs[j + 1]);
        int s2 = __ldg(&srcs[j + 2]);
        int s3 = __ldg(&srcs[j + 3]);
        float4 v0 = *(const float4*)&H[(size_t)s0 * 256 + off + lane * 4];
        float4 v1 = *(const float4*)&H[(size_t)s1 * 256 + off + lane * 4];
        float4 v2 = *(const float4*)&H[(size_t)s2 * 256 + off + lane * 4];
        float4 v3 = *(const float4*)&H[(size_t)s3 * 256 + off + lane * 4];
        a0.x += v0.x; a0.y += v0.y; a0.z += v0.z; a0.w += v0.w;
        a1.x += v1.x; a1.y += v1.y; a1.z += v1.z; a1.w += v1.w;
        a0.x += v2.x; a0.y += v2.y; a0.z += v2.z; a0.w += v2.w;
        a1.x += v3.x; a1.y += v3.y; a1.z += v3.z; a1.w += v3.w;
    }
    for (; j < end; j++) {
        int s0 = __ldg(&srcs[j]);
        float4 v0 = *(const float4*)&H[(size_t)s0 * 256 + off + lane * 4];
        a0.x += v0.x; a0.y += v0.y; a0.z += v0.z; a0.w += v0.w;
    }
    a0.x += a1.x; a0.y += a1.y; a0.z += a1.z; a0.w += a1.w;
    *(float4*)&AG[(size_t)node * 64 + lane * 4] = a0;
}

// ================= HMMA GEMM, 256 threads, 256-ROW tile (m32n64 per warp) =================
// smem: A_hi[0,32K) A_lo[32K,64K) B_hi[64K,72K) B_lo[72K,80K); epilogue stage reuses [0,69632).
#define DYN_SMEM 83968
__global__ __launch_bounds__(256) void k_gemm_mma(
    const float* __restrict__ A, int lda, int ktiles, int wslot,
    const float* __restrict__ bias, const float* __restrict__ statsPrev,
    const float* __restrict__ gPrev, const float* __restrict__ bePrev, float* __restrict__ Z,
    float* __restrict__ stats, int guardA, const __nv_bfloat16* __restrict__ Whi,
    const __nv_bfloat16* __restrict__ Wlo) {
    extern __shared__ __align__(16) char dsm[];
    __shared__ float sPar[192];
    int tid = threadIdx.x;
    uint32_t raw = s2u(dsm);
    uint32_t base0 = (raw + 1023) & ~1023u;
    char* bp = dsm + (base0 - raw);

    if (tid < 64) {
        sPar[tid] = bias[tid];
        if (statsPrev) {
            float inv = 1.0f / (float)N_NODES;
            float m = statsPrev[tid] * inv;
            float v = fmaxf(statsPrev[64 + tid] * inv - m * m, 0.f);
            float s = gPrev[tid] * rsqrtf(v + BN_EPS);
            sPar[64 + tid] = s;
            sPar[128 + tid] = bePrev[tid] - m * s;
        }
    }
    int row0 = blockIdx.x * 256;
    int w = tid >> 5, lane = tid & 31;

    uint32_t aRB[2], aX[2];
#pragma unroll
    for (int g = 0; g < 2; g++) {
        int arow = 32 * w + 16 * g + (lane & 7) + (lane & 8);
        aRB[g] = base0 + (uint32_t)arow * 128;
        aX[g] = (uint32_t)(arow & 7) << 4;
    }
    uint32_t aColSel = ((lane >> 4) & 1) * 16;
    int browBase = (lane & 7) + ((lane >> 4) & 1) * 8;
    uint32_t bXor = (uint32_t)(browBase & 7) << 4;
    uint32_t bColSel = ((lane >> 3) & 1) * 16;

    float acc[8][8];
#pragma unroll
    for (int i = 0; i < 8; i++)
#pragma unroll
        for (int j = 0; j < 8; j++) acc[i][j] = 0.f;

    for (int kt = 0; kt < ktiles; kt++) {
        __syncthreads();
#pragma unroll 4
        for (int it = 0; it < 16; it++) {
            int idx = tid + it * 256;
            int r = idx >> 4, f4 = idx & 15;
            int row = row0 + r;
            float4 v = make_float4(0.f, 0.f, 0.f, 0.f);
            if (!guardA || row < N_NODES)
                v = *(const float4*)&A[(size_t)row * lda + kt * 64 + f4 * 4];
            if (statsPrev) {
                int c = f4 * 4;
                v.x = fmaxf(v.x * sPar[64 + c] + sPar[128 + c], 0.f);
                v.y = fmaxf(v.y * sPar[65 + c] + sPar[129 + c], 0.f);
                v.z = fmaxf(v.z * sPar[66 + c] + sPar[130 + c], 0.f);
                v.w = fmaxf(v.w * sPar[67 + c] + sPar[131 + c], 0.f);
            }
            __nv_bfloat162 h0 = __float22bfloat162_rn(make_float2(v.x, v.y));
            __nv_bfloat162 h1 = __float22bfloat162_rn(make_float2(v.z, v.w));
            float2 r0 = __bfloat1622float2(h0);
            float2 r1 = __bfloat1622float2(h1);
            __nv_bfloat162 l0 = __float22bfloat162_rn(make_float2(v.x - r0.x, v.y - r0.y));
            __nv_bfloat162 l1 = __float22bfloat162_rn(make_float2(v.z - r1.x, v.w - r1.y));
            uint32_t sw = swz((uint32_t)r * 128 + (uint32_t)f4 * 8);
            *(uint2*)(bp + sw) = make_uint2(*(uint32_t*)&h0, *(uint32_t*)&h1);
            *(uint2*)(bp + 32768 + sw) = make_uint2(*(uint32_t*)&l0, *(uint32_t*)&l1);
        }
        const __nv_bfloat16* wh = Whi + (size_t)(wslot + kt) * 4096;
        const __nv_bfloat16* wl = Wlo + (size_t)(wslot + kt) * 4096;
#pragma unroll
        for (int it = 0; it < 2; it++) {
            int idx = tid + it * 256;
            int n = idx >> 3, f8 = idx & 7;
            uint32_t sw = swz((uint32_t)n * 128 + (uint32_t)f8 * 16);
            *(uint4*)(bp + 65536 + sw) = *(const uint4*)&wh[n * 64 + f8 * 8];
            *(uint4*)(bp + 73728 + sw) = *(const uint4*)&wl[n * 64 + f8 * 8];
        }
        __syncthreads();

#pragma unroll
        for (int kc = 0; kc < 4; kc++) {
            uint32_t ac = (aColSel + (uint32_t)kc * 32);
            uint32_t ah[2][4], al[2][4];
#pragma unroll
            for (int g = 0; g < 2; g++) {
                LDSM_X4(ah[g][0], ah[g][1], ah[g][2], ah[g][3], aRB[g] + (ac ^ aX[g]));
                LDSM_X4(al[g][0], al[g][1], al[g][2], al[g][3], aRB[g] + 32768 + (ac ^ aX[g]));
            }
#pragma unroll
            for (int np = 0; np < 4; np++) {
                uint32_t boff = (uint32_t)(browBase + np * 16) * 128 +
                                (((uint32_t)kc * 32 + bColSel) ^ bXor);
                uint32_t bh0, bh1, bh2, bh3, bl0, bl1, bl2, bl3;
                LDSM_X4(bh0, bh1, bh2, bh3, base0 + 65536 + boff);
                LDSM_X4(bl0, bl1, bl2, bl3, base0 + 73728 + boff);
#pragma unroll
                for (int g = 0; g < 2; g++) {
                    float* a4 = acc[g * 4 + np];
                    MMA(a4, ah[g][0], ah[g][1], ah[g][2], ah[g][3], bh0, bh1);
                    MMA(a4, ah[g][0], ah[g][1], ah[g][2], ah[g][3], bl0, bl1);
                    MMA(a4, al[g][0], al[g][1], al[g][2], al[g][3], bh0, bh1);
                    MMA(a4 + 4, ah[g][0], ah[g][1], ah[g][2], ah[g][3], bh2, bh3);
                    MMA(a4 + 4, ah[g][0], ah[g][1], ah[g][2], ah[g][3], bl2, bl3);
                    MMA(a4 + 4, al[g][0], al[g][1], al[g][2], al[g][3], bh2, bh3);
                }
            }
        }
    }
    __syncthreads();

    float* stage = (float*)bp;
    int grp = lane >> 2, tg = lane & 3;
#pragma unroll
    for (int g = 0; g < 2; g++) {
        int rA = 32 * w + 16 * g + grp;
#pragma unroll
        for (int np = 0; np < 4; np++) {
            float* a4 = acc[g * 4 + np];
#pragma unroll
            for (int t = 0; t < 2; t++) {
                int col = np * 16 + t * 8 + tg * 2;
                stage[rA * 68 + col] = a4[t * 4 + 0] + sPar[col];
                stage[rA * 68 + col + 1] = a4[t * 4 + 1] + sPar[col + 1];
                stage[(rA + 8) * 68 + col] = a4[t * 4 + 2] + sPar[col];
                stage[(rA + 8) * 68 + col + 1] = a4[t * 4 + 3] + sPar[col + 1];
            }
        }
    }
    __syncthreads();
    {
        int row = row0 + tid;
        if (row >= N_NODES) {
#pragma unroll
            for (int f4 = 0; f4 < 16; f4++)
                *(float4*)&stage[tid * 68 + f4 * 4] = make_float4(0.f, 0.f, 0.f, 0.f);
        }
    }
    __syncthreads();
#pragma unroll 4
    for (int it = 0; it < 16; it++) {
        int idx = tid + it * 256;
        int r = idx >> 4, f4 = idx & 15;
        int rw = row0 + r;
        if (rw < N_NODES)
            *(float4*)&Z[(size_t)rw * 64 + f4 * 4] = *(float4*)&stage[r * 68 + f4 * 4];
    }
    int c = tid & 63, q = tid >> 6;
    float sum = 0.f, sq = 0.f;
#pragma unroll 8
    for (int rr = 0; rr < 64; rr++) {
        float x = stage[(q * 64 + rr) * 68 + c];
        sum += x;
        sq += x * x;
    }
    atomicAdd(&stats[c], sum);
    atomicAdd(&stats[64 + c], sq);
}

// ----------- merged stats + double-affine H writer, SINGLE Z pass via smem cache ----------
// dyn smem: cache[256*68]f = 69632 B; static ~1.1 KB (NO sred — shuffle + direct RED).
// Residency: 70.7 KB/block -> 3 blocks/SM x 148 = 444 >= 391 (gsync safe); 768 thr/SM ok.
#define SW_SMEM (256 * 68 * 4)
__global__ __launch_bounds__(256) void k_statwrite(
    const float* __restrict__ Z, const float* __restrict__ stA, const float* __restrict__ gA,
    const float* __restrict__ beA, const float* __restrict__ gB,
    const float* __restrict__ beB, float* __restrict__ H, int off,
    float* __restrict__ statsOut, float* __restrict__ scbuf, int* __restrict__ ctr) {
    extern __shared__ __align__(16) float cache[];  // [r*68 + c]
    __shared__ float aff[128];
    __shared__ float affB[128];
    __shared__ int isLast;
    int tid = threadIdx.x;
    float inv = 1.0f / (float)N_NODES;
    if (tid < 64) {
        float m = stA[tid] * inv;
        float v = fmaxf(stA[64 + tid] * inv - m * m, 0.f);
        float s = gA[tid] * rsqrtf(v + BN_EPS);
        aff[tid] = s;
        aff[64 + tid] = beA[tid] - m * s;
    }
    __syncthreads();

    int row0 = blockIdx.x * 256;
    int rsub = tid >> 4, c0 = (tid & 15) * 4;
    float ps[4] = {}, pq[4] = {};
#pragma unroll 4
    for (int it = 0; it < 16; it++) {
        int r = row0 + it * 16 + rsub;
        if (r < N_NODES) {
            float4 z = *(const float4*)&Z[(size_t)r * 64 + c0];
            float a0 = fmaxf(z.x * aff[c0 + 0] + aff[64 + c0 + 0], 0.f);
            float a1 = fmaxf(z.y * aff[c0 + 1] + aff[64 + c0 + 1], 0.f);
            float a2 = fmaxf(z.z * aff[c0 + 2] + aff[64 + c0 + 2], 0.f);
            float a3 = fmaxf(z.w * aff[c0 + 3] + aff[64 + c0 + 3], 0.f);
            *(float4*)&cache[(it * 16 + rsub) * 68 + c0] = make_float4(a0, a1, a2, a3);
            ps[0] += a0; pq[0] += a0 * a0;
            ps[1] += a1; pq[1] += a1 * a1;
            ps[2] += a2; pq[2] += a2 * a2;
            ps[3] += a3; pq[3] += a3 * a3;
        }
    }
    // lanes l and l^16 share c0 -> combine, then lanes 0-15 RED to global (result unused)
#pragma unroll
    for (int j = 0; j < 4; j++) {
        ps[j] += __shfl_xor_sync(0xffffffffu, ps[j], 16);
        pq[j] += __shfl_xor_sync(0xffffffffu, pq[j], 16);
    }
    if ((tid & 31) < 16) {
#pragma unroll
        for (int j = 0; j < 4; j++) {
            atomicAdd(&statsOut[c0 + j], ps[j]);
            atomicAdd(&statsOut[64 + c0 + j], pq[j]);
        }
    }
    __threadfence();
    __syncthreads();
    if (tid == 0) {
        int old = atomicAdd(ctr, 1);
        isLast = (old == (int)gridDim.x - 1);
    }
    __syncthreads();
    if (isLast) {
        if (tid < 64) {
            float m = statsOut[tid] * inv;
            float v = fmaxf(statsOut[64 + tid] * inv - m * m, 0.f);
            float s = gB[tid] * rsqrtf(v + BN_EPS);
            scbuf[tid] = s;
            scbuf[64 + tid] = beB[tid] - m * s;
        }
        __threadfence();
        __syncthreads();
        if (tid == 0) atomicExch(ctr, DONE_FLAG);
    } else {
        if (tid == 0) {
            while (atomicAdd(ctr, 0) != DONE_FLAG) __nanosleep(64);
        }
        __syncthreads();
    }
    __threadfence();
    if (tid < 64) {
        affB[tid] = scbuf[tid];
        affB[64 + tid] = scbuf[64 + tid];
    }
    __syncthreads();

    // write pass: only affine-B on cached a-values (no Z re-read)
#pragma unroll 4
    for (int it = 0; it < 16; it++) {
        int r = row0 + it * 16 + rsub;
        if (r < N_NODES) {
            float4 a = *(const float4*)&cache[(it * 16 + rsub) * 68 + c0];
            float o[4] = {a.x, a.y, a.z, a.w};
#pragma unroll
            for (int j = 0; j < 4; j++)
                o[j] = fmaxf(o[j] * affB[c0 + j] + affB[64 + c0 + j], 0.f);
            *(float4*)&H[(size_t)r * 256 + off + c0] = make_float4(o[0], o[1], o[2], o[3]);
        }
    }
}

// ----------------- H-slice writer (single affine; input layer) -----------------
__global__ void k_hwrite(const float* __restrict__ Z, const float* __restrict__ stA,
                         const float* __restrict__ gA, const float* __restrict__ beA,
                         float* __restrict__ H, int off) {
    __shared__ float aff[128];
    int tid = threadIdx.x;
    if (tid < 64) {
        float inv = 1.0f / (float)N_NODES;
        float m = stA[tid] * inv;
        float v = fmaxf(stA[64 + tid] * inv - m * m, 0.f);
        float s = gA[tid] * rsqrtf(v + BN_EPS);
        aff[tid] = s;
        aff[64 + tid] = beA[tid] - m * s;
    }
    __syncthreads();
    int r = blockIdx.x * 16 + (tid >> 4);
    int c0 = (tid & 15) * 4;
    float4 z = *(const float4*)&Z[(size_t)r * 64 + c0];
    float o[4] = {z.x, z.y, z.z, z.w};
#pragma unroll
    for (int j = 0; j < 4; j++) o[j] = fmaxf(o[j] * aff[c0 + j] + aff[64 + c0 + j], 0.f);
    *(float4*)&H[(size_t)r * 256 + off + c0] = make_float4(o[0], o[1], o[2], o[3]);
}

// ----------------- final readout -----------------
__global__ void k_out(const float* __restrict__ Z, const float* __restrict__ stA,
                      const float* __restrict__ gA, const float* __restrict__ beA,
                      const float* __restrict__ W2, const float* __restrict__ b2,
                      float* __restrict__ out) {
    __shared__ float Ws[640];
    __shared__ float bs[10];
    __shared__ float ss[64], tt[64];
    int tid = threadIdx.x;
    for (int i = tid; i < 640; i += 256) Ws[i] = W2[i];
    if (tid < 10) bs[tid] = b2[tid];
    if (tid < 64) {
        float inv = 1.0f / (float)N_NODES;
        float m = stA[tid] * inv;
        float v = fmaxf(stA[64 + tid] * inv - m * m, 0.f);
        float s = gA[tid] * rsqrtf(v + BN_EPS);
        ss[tid] = s;
        tt[tid] = beA[tid] - m * s;
    }
    __syncthreads();
    int row = blockIdx.x * 256 + tid;
    if (row >= N_NODES) return;
    float o[10];
#pragma unroll
    for (int j = 0; j < 10; j++) o[j] = bs[j];
    const float4* zp = (const float4*)(Z + (size_t)row * 64);
#pragma unroll
    for (int i = 0; i < 16; i++) {
        float4 v = zp[i];
        int c = i * 4;
        float a0 = fmaxf(v.x * ss[c + 0] + tt[c + 0], 0.f);
        float a1 = fmaxf(v.y * ss[c + 1] + tt[c + 1], 0.f);
        float a2 = fmaxf(v.z * ss[c + 2] + tt[c + 2], 0.f);
        float a3 = fmaxf(v.w * ss[c + 3] + tt[c + 3], 0.f);
#pragma unroll
        for (int j = 0; j < 10; j++)
            o[j] += a0 * Ws[(c + 0) * 10 + j] + a1 * Ws[(c + 1) * 10 + j] +
                    a2 * Ws[(c + 2) * 10 + j] + a3 * Ws[(c + 3) * 10 + j];
    }
#pragma unroll
    for (int j = 0; j < 10; j++) out[(size_t)row * 10 + j] = o[j];
}

// ============================ host ============================
extern "C" void kernel_launch(void* const* d_in, const int* in_sizes, int n_in, void* d_out,
                              int out_size) {
    const float* x = (const float*)d_in[0];
    const int* ei = (const int*)d_in[1];
    const float* W_in = (const float*)d_in[2];
    const float* b_in = (const float*)d_in[3];
    const float* g_in = (const float*)d_in[4];
    const float* be_in = (const float*)d_in[5];
    const float* eps = (const float*)d_in[6];
    const float* W1 = (const float*)d_in[7];
    const float* b1 = (const float*)d_in[8];
    const float* g1 = (const float*)d_in[9];
    const float* be1 = (const float*)d_in[10];
    const float* W2 = (const float*)d_in[11];
    const float* b2 = (const float*)d_in[12];
    const float* g2 = (const float*)d_in[13];
    const float* be2 = (const float*)d_in[14];
    const float* g_post = (const float*)d_in[15];
    const float* be_post = (const float*)d_in[16];
    const float* W_out1 = (const float*)d_in[17];
    const float* b_out1 = (const float*)d_in[18];
    const float* g_out = (const float*)d_in[19];
    const float* be_out = (const float*)d_in[20];
    const float* W_out2 = (const float*)d_in[21];
    const float* b_out2 = (const float*)d_in[22];
    float* out = (float*)d_out;

    float *H, *T1, *T2, *AG, *ST, *SC;
    __nv_bfloat16 *Whi, *Wlo;
    int *cnt, *excl, *rowptr, *cursor, *srcs, *bsum, *sync;
    cudaGetSymbolAddress((void**)&H, g_H);
    cudaGetSymbolAddress((void**)&T1, g_T1);
    cudaGetSymbolAddress((void**)&T2, g_T2);
    cudaGetSymbolAddress((void**)&AG, g_AG);
    cudaGetSymbolAddress((void**)&ST, g_stats);
    cudaGetSymbolAddress((void**)&SC, g_scale);
    cudaGetSymbolAddress((void**)&Whi, g_Whi);
    cudaGetSymbolAddress((void**)&Wlo, g_Wlo);
    cudaGetSymbolAddress((void**)&cnt, g_cnt);
    cudaGetSymbolAddress((void**)&excl, g_excl);
    cudaGetSymbolAddress((void**)&rowptr, g_rowptr);
    cudaGetSymbolAddress((void**)&cursor, g_cursor);
    cudaGetSymbolAddress((void**)&srcs, g_srcs);
    cudaGetSymbolAddress((void**)&bsum, g_bsum);
    cudaGetSymbolAddress((void**)&sync, g_sync);

    cudaFuncSetAttribute(k_gemm_mma, cudaFuncAttributeMaxDynamicSharedMemorySize, DYN_SMEM);
    cudaFuncSetAttribute(k_statwrite, cudaFuncAttributeMaxDynamicSharedMemorySize, SW_SMEM);

    const int P_GRID = N_PAD / 256;              // 391
    const int EDGE_GRID = N_EDGES / 256;         // 6250
    const int NODE16_GRID = N_NODES * 16 / 256;  // 6250
    const int HW_GRID = N_NODES / 16;            // 6250

    // 1: init   2: hist   3: scan1+blockscan
    k_init<<<400, 256>>>(ST, cnt, T1, T2, AG, H, sync, W_in, W1, W2, W_out1, Whi, Wlo);
    k_hist<<<EDGE_GRID, 256>>>(ei, cnt);
    k_scan1m<<<CSR_GRID, SCAN_B>>>(cnt, excl, bsum, &sync[0]);
    // 4: input projection GEMM (independent of CSR — ncu -s 5 profiles it)
    k_gemm_mma<<<P_GRID, 256, DYN_SMEM>>>(x, 64, 1, 0, b_in, nullptr, nullptr, nullptr, T1,
                                          ST + 0 * 128, 1, Whi, Wlo);
    // 5: scan3   6: fill   7: h0 -> H slice 0
    k_scan3<<<CSR_GRID, SCAN_B>>>(excl, bsum, rowptr, cursor);
    k_fill<<<EDGE_GRID, 256>>>(ei, cursor, srcs);
    k_hwrite<<<HW_GRID, 256>>>(T1, ST + 0 * 128, g_in, be_in, H, 0);

    for (int i = 0; i < NLAYER; i++) {
        int off = i * 64;
        int s1 = 1 + 3 * i, s2 = 2 + 3 * i, s3 = 3 + 3 * i;
        k_aggr<<<NODE16_GRID, 256>>>(rowptr, srcs, H, off, eps, i, AG);
        k_gemm_mma<<<P_GRID, 256, DYN_SMEM>>>(AG, 64, 1, 1 + i, b1 + i * 64, nullptr, nullptr,
                                              nullptr, T1, ST + s1 * 128, 0, Whi, Wlo);
        k_gemm_mma<<<P_GRID, 256, DYN_SMEM>>>(T1, 64, 1, 4 + i, b2 + i * 64, ST + s1 * 128,
                                              g1 + i * 64, be1 + i * 64, T2, ST + s2 * 128, 0,
                                              Whi, Wlo);
        k_statwrite<<<RS_GRID, 256, SW_SMEM>>>(T2, ST + s2 * 128, g2 + i * 64, be2 + i * 64,
                                               g_post + i * 64, be_post + i * 64, H, off + 64,
                                               ST + s3 * 128, SC + i * 128, &sync[4 + i]);
    }

    // readout (K=256)
    k_gemm_mma<<<P_GRID, 256, DYN_SMEM>>>(H, 256, 4, 7, b_out1, nullptr, nullptr, nullptr, T1,
                                          ST + 10 * 128, 0, Whi, Wlo);
    k_out<<<RS_GRID, 256>>>(T1, ST + 10 * 128, g_out, be_out, W_out2, b_out2, out);

    (void)in_sizes; (void)n_in; (void)out_size;
}

// round 16
// speedup vs baseline: 1.4440x; 1.4440x over previous
#include <cuda_runtime.h>
#include <cuda_bf16.h>
#include <cstdint>

#define N_NODES 100000
#define N_PAD 100096          // 391 * 256
#define N_EDGES 1600000
#define NLAYER 3
#define BN_EPS 1e-5f
#define SCAN_B 1024
#define CSR_GRID 98
#define RS_GRID 391
#define DONE_FLAG (-12345)

// -------- scratch (static device globals; allocation-free) --------
__device__ float g_H[(size_t)N_PAD * 256];
__device__ float g_T1[(size_t)N_PAD * 64];
__device__ float g_T2[(size_t)N_PAD * 64];
__device__ float g_AG[(size_t)N_PAD * 64];
__device__ float g_stats[11 * 128];
__device__ float g_scale[NLAYER * 128];
__device__ int g_sync[16];
__device__ __nv_bfloat16 g_Whi[11 * 4096];
__device__ __nv_bfloat16 g_Wlo[11 * 4096];
__device__ int g_cnt[N_NODES];
__device__ int g_excl[N_NODES];
__device__ int g_rowptr[N_NODES + 1];
__device__ int g_cursor[N_NODES];
__device__ int g_srcs[N_EDGES];
__device__ int g_bsum[CSR_GRID];

__device__ __forceinline__ uint32_t s2u(const void* p) {
    uint32_t a;
    asm("{ .reg .u64 t; cvta.to.shared.u64 t, %1; cvt.u32.u64 %0, t; }" : "=r"(a) : "l"(p));
    return a;
}
static __device__ __forceinline__ uint32_t swz(uint32_t off) { return off ^ ((off >> 3) & 0x70); }

#define LDSM_X4(r0, r1, r2, r3, addr)                                                          \
    asm volatile("ldmatrix.sync.aligned.m8n8.x4.shared.b16 {%0,%1,%2,%3}, [%4];"               \
                 : "=r"(r0), "=r"(r1), "=r"(r2), "=r"(r3)                                      \
                 : "r"(addr))
#define MMA(dst, a0, a1, a2, a3, b0, b1)                                                       \
    asm volatile(                                                                              \
        "mma.sync.aligned.m16n8k16.row.col.f32.bf16.bf16.f32 "                                 \
        "{%0,%1,%2,%3},{%4,%5,%6,%7},{%8,%9},{%0,%1,%2,%3};"                                   \
        : "+f"((dst)[0]), "+f"((dst)[1]), "+f"((dst)[2]), "+f"((dst)[3])                       \
        : "r"(a0), "r"(a1), "r"(a2), "r"(a3), "r"(b0), "r"(b1))

// ----------------- init: zero scratch + sync counters + weight transpose/split ----------
__global__ void k_init(float* stats, int* cnt, float* T1, float* T2, float* AG, float* H,
                       int* sync, const float* __restrict__ W_in, const float* __restrict__ W1,
                       const float* __restrict__ W2, const float* __restrict__ W_out1,
                       __nv_bfloat16* __restrict__ hi, __nv_bfloat16* __restrict__ lo) {
    int i = blockIdx.x * 256 + threadIdx.x;
    if (i < 11 * 128) stats[i] = 0.f;
    if (i < 16) sync[i] = 0;
    if (i < N_NODES) cnt[i] = 0;
    if (i < (N_PAD - N_NODES) * 64) {
        T1[(size_t)N_NODES * 64 + i] = 0.f;
        T2[(size_t)N_NODES * 64 + i] = 0.f;
        AG[(size_t)N_NODES * 64 + i] = 0.f;
    }
    if (i < (N_PAD - N_NODES) * 256) H[(size_t)N_NODES * 256 + i] = 0.f;
    if (i < 11 * 4096) {
        int slot = i >> 12, within = i & 4095;
        int n = within >> 6, k = within & 63;
        float v;
        if (slot == 0) v = W_in[k * 64 + n];
        else if (slot <= 3) v = W1[(slot - 1) * 4096 + k * 64 + n];
        else if (slot <= 6) v = W2[(slot - 4) * 4096 + k * 64 + n];
        else v = W_out1[((slot - 7) * 64 + k) * 64 + n];
        __nv_bfloat16 h = __float2bfloat16(v);
        hi[i] = h;
        lo[i] = __float2bfloat16(v - __bfloat162float(h));
    }
}

// ----------------- CSR build -----------------
__global__ void k_hist(const int* __restrict__ ei, int* __restrict__ cnt) {
    int e = blockIdx.x * 256 + threadIdx.x;
    atomicAdd(&cnt[ei[N_EDGES + e]], 1);
}
__global__ __launch_bounds__(SCAN_B) void k_scan1m(const int* __restrict__ cnt,
                                                   int* __restrict__ excl,
                                                   int* __restrict__ bsum,
                                                   int* __restrict__ ctr) {
    __shared__ int sm[SCAN_B];
    __shared__ int isLast;
    int tid = threadIdx.x;
    int i = blockIdx.x * SCAN_B + tid;
    int v = (i < N_NODES) ? cnt[i] : 0;
    sm[tid] = v;
    __syncthreads();
    for (int ofs = 1; ofs < SCAN_B; ofs <<= 1) {
        int t = (tid >= ofs) ? sm[tid - ofs] : 0;
        __syncthreads();
        sm[tid] += t;
        __syncthreads();
    }
    if (i < N_NODES) excl[i] = sm[tid] - v;
    if (tid == SCAN_B - 1) bsum[blockIdx.x] = sm[tid];
    __threadfence();
    __syncthreads();
    if (tid == 0) {
        int old = atomicAdd(ctr, 1);
        isLast = (old == CSR_GRID - 1);
    }
    __syncthreads();
    if (!isLast) return;
    int bv = (tid < CSR_GRID) ? bsum[tid] : 0;
    sm[tid] = bv;
    __syncthreads();
    for (int ofs = 1; ofs < 128; ofs <<= 1) {
        int t = (tid >= ofs && tid < 128) ? sm[tid - ofs] : 0;
        __syncthreads();
        if (tid < 128) sm[tid] += t;
        __syncthreads();
    }
    if (tid < CSR_GRID) bsum[tid] = sm[tid] - bv;
}
__global__ void k_scan3(const int* __restrict__ excl, const int* __restrict__ bsum,
                        int* __restrict__ rowptr, int* __restrict__ cursor) {
    int i = blockIdx.x * SCAN_B + threadIdx.x;
    if (i < N_NODES) {
        int r = excl[i] + bsum[blockIdx.x];
        rowptr[i] = r;
        cursor[i] = r;
    }
    if (i == 0) rowptr[N_NODES] = N_EDGES;
}
__global__ void k_fill(const int* __restrict__ ei, int* __restrict__ cursor,
                       int* __restrict__ srcs) {
    int e = blockIdx.x * 256 + threadIdx.x;
    int pos = atomicAdd(&cursor[ei[N_EDGES + e]], 1);
    srcs[pos] = ei[e];
}

// ----------------- CSR aggregation (max-parallel, 4-wide unrolled gather) -----------------
__global__ void k_aggr(const int* __restrict__ rowptr, const int* __restrict__ srcs,
                       const float* __restrict__ H, int off, const float* __restrict__ eps,
                       int li, float* __restrict__ AG) {
    int g = blockIdx.x * 256 + threadIdx.x;
    int node = g >> 4, lane = g & 15;
    float e = 1.f + eps[li];
    float4 self = *(const float4*)&H[(size_t)node * 256 + off + lane * 4];
    float4 a0 = make_float4(e * self.x, e * self.y, e * self.z, e * self.w);
    float4 a1 = make_float4(0.f, 0.f, 0.f, 0.f);
    int beg = rowptr[node], end = rowptr[node + 1];
    int j = beg;
    for (; j + 4 <= end; j += 4) {
        int s0 = __ldg(&srcs[j]);
        int s1 = __ldg(&srcs[j + 1]);
        int s2 = __ldg(&srcs[j + 2]);
        int s3 = __ldg(&srcs[j + 3]);
        float4 v0 = *(const float4*)&H[(size_t)s0 * 256 + off + lane * 4];
        float4 v1 = *(const float4*)&H[(size_t)s1 * 256 + off + lane * 4];
        float4 v2 = *(const float4*)&H[(size_t)s2 * 256 + off + lane * 4];
        float4 v3 = *(const float4*)&H[(size_t)s3 * 256 + off + lane * 4];
        a0.x += v0.x; a0.y += v0.y; a0.z += v0.z; a0.w += v0.w;
        a1.x += v1.x; a1.y += v1.y; a1.z += v1.z; a1.w += v1.w;
        a0.x += v2.x; a0.y += v2.y; a0.z += v2.z; a0.w += v2.w;
        a1.x += v3.x; a1.y += v3.y; a1.z += v3.z; a1.w += v3.w;
    }
    for (; j < end; j++) {
        int s0 = __ldg(&srcs[j]);
        float4 v0 = *(const float4*)&H[(size_t)s0 * 256 + off + lane * 4];
        a0.x += v0.x; a0.y += v0.y; a0.z += v0.z; a0.w += v0.w;
    }
    a0.x += a1.x; a0.y += a1.y; a0.z += a1.z; a0.w += a1.w;
    *(float4*)&AG[(size_t)node * 64 + lane * 4] = a0;
}

// ================= HMMA GEMM, 256 threads, 256-ROW tile (m32n64 per warp) =================
// smem: A_hi[0,32K) A_lo[32K,64K) B_hi[64K,72K) B_lo[72K,80K); epilogue stage reuses [0,69632).
#define DYN_SMEM 83968
__global__ __launch_bounds__(256) void k_gemm_mma(
    const float* __restrict__ A, int lda, int ktiles, int wslot,
    const float* __restrict__ bias, const float* __restrict__ statsPrev,
    const float* __restrict__ gPrev, const float* __restrict__ bePrev, float* __restrict__ Z,
    float* __restrict__ stats, int guardA, const __nv_bfloat16* __restrict__ Whi,
    const __nv_bfloat16* __restrict__ Wlo) {
    extern __shared__ __align__(16) char dsm[];
    __shared__ float sPar[192];
    int tid = threadIdx.x;
    uint32_t raw = s2u(dsm);
    uint32_t base0 = (raw + 1023) & ~1023u;
    char* bp = dsm + (base0 - raw);

    if (tid < 64) {
        sPar[tid] = bias[tid];
        if (statsPrev) {
            float inv = 1.0f / (float)N_NODES;
            float m = statsPrev[tid] * inv;
            float v = fmaxf(statsPrev[64 + tid] * inv - m * m, 0.f);
            float s = gPrev[tid] * rsqrtf(v + BN_EPS);
            sPar[64 + tid] = s;
            sPar[128 + tid] = bePrev[tid] - m * s;
        }
    }
    int row0 = blockIdx.x * 256;
    int w = tid >> 5, lane = tid & 31;

    uint32_t aRB[2], aX[2];
#pragma unroll
    for (int g = 0; g < 2; g++) {
        int arow = 32 * w + 16 * g + (lane & 7) + (lane & 8);
        aRB[g] = base0 + (uint32_t)arow * 128;
        aX[g] = (uint32_t)(arow & 7) << 4;
    }
    uint32_t aColSel = ((lane >> 4) & 1) * 16;
    int browBase = (lane & 7) + ((lane >> 4) & 1) * 8;
    uint32_t bXor = (uint32_t)(browBase & 7) << 4;
    uint32_t bColSel = ((lane >> 3) & 1) * 16;

    float acc[8][8];
#pragma unroll
    for (int i = 0; i < 8; i++)
#pragma unroll
        for (int j = 0; j < 8; j++) acc[i][j] = 0.f;

    for (int kt = 0; kt < ktiles; kt++) {
        __syncthreads();
#pragma unroll 4
        for (int it = 0; it < 16; it++) {
            int idx = tid + it * 256;
            int r = idx >> 4, f4 = idx & 15;
            int row = row0 + r;
            float4 v = make_float4(0.f, 0.f, 0.f, 0.f);
            if (!guardA || row < N_NODES)
                v = *(const float4*)&A[(size_t)row * lda + kt * 64 + f4 * 4];
            if (statsPrev) {
                int c = f4 * 4;
                v.x = fmaxf(v.x * sPar[64 + c] + sPar[128 + c], 0.f);
                v.y = fmaxf(v.y * sPar[65 + c] + sPar[129 + c], 0.f);
                v.z = fmaxf(v.z * sPar[66 + c] + sPar[130 + c], 0.f);
                v.w = fmaxf(v.w * sPar[67 + c] + sPar[131 + c], 0.f);
            }
            __nv_bfloat162 h0 = __float22bfloat162_rn(make_float2(v.x, v.y));
            __nv_bfloat162 h1 = __float22bfloat162_rn(make_float2(v.z, v.w));
            float2 r0 = __bfloat1622float2(h0);
            float2 r1 = __bfloat1622float2(h1);
            __nv_bfloat162 l0 = __float22bfloat162_rn(make_float2(v.x - r0.x, v.y - r0.y));
            __nv_bfloat162 l1 = __float22bfloat162_rn(make_float2(v.z - r1.x, v.w - r1.y));
            uint32_t sw = swz((uint32_t)r * 128 + (uint32_t)f4 * 8);
            *(uint2*)(bp + sw) = make_uint2(*(uint32_t*)&h0, *(uint32_t*)&h1);
            *(uint2*)(bp + 32768 + sw) = make_uint2(*(uint32_t*)&l0, *(uint32_t*)&l1);
        }
        const __nv_bfloat16* wh = Whi + (size_t)(wslot + kt) * 4096;
        const __nv_bfloat16* wl = Wlo + (size_t)(wslot + kt) * 4096;
#pragma unroll
        for (int it = 0; it < 2; it++) {
            int idx = tid + it * 256;
            int n = idx >> 3, f8 = idx & 7;
            uint32_t sw = swz((uint32_t)n * 128 + (uint32_t)f8 * 16);
            *(uint4*)(bp + 65536 + sw) = *(const uint4*)&wh[n * 64 + f8 * 8];
            *(uint4*)(bp + 73728 + sw) = *(const uint4*)&wl[n * 64 + f8 * 8];
        }
        __syncthreads();

#pragma unroll
        for (int kc = 0; kc < 4; kc++) {
            uint32_t ac = (aColSel + (uint32_t)kc * 32);
            uint32_t ah[2][4], al[2][4];
#pragma unroll
            for (int g = 0; g < 2; g++) {
                LDSM_X4(ah[g][0], ah[g][1], ah[g][2], ah[g][3], aRB[g] + (ac ^ aX[g]));
                LDSM_X4(al[g][0], al[g][1], al[g][2], al[g][3], aRB[g] + 32768 + (ac ^ aX[g]));
            }
#pragma unroll
            for (int np = 0; np < 4; np++) {
                uint32_t boff = (uint32_t)(browBase + np * 16) * 128 +
                                (((uint32_t)kc * 32 + bColSel) ^ bXor);
                uint32_t bh0, bh1, bh2, bh3, bl0, bl1, bl2, bl3;
                LDSM_X4(bh0, bh1, bh2, bh3, base0 + 65536 + boff);
                LDSM_X4(bl0, bl1, bl2, bl3, base0 + 73728 + boff);
#pragma unroll
                for (int g = 0; g < 2; g++) {
                    float* a4 = acc[g * 4 + np];
                    MMA(a4, ah[g][0], ah[g][1], ah[g][2], ah[g][3], bh0, bh1);
                    MMA(a4, ah[g][0], ah[g][1], ah[g][2], ah[g][3], bl0, bl1);
                    MMA(a4, al[g][0], al[g][1], al[g][2], al[g][3], bh0, bh1);
                    MMA(a4 + 4, ah[g][0], ah[g][1], ah[g][2], ah[g][3], bh2, bh3);
                    MMA(a4 + 4, ah[g][0], ah[g][1], ah[g][2], ah[g][3], bl2, bl3);
                    MMA(a4 + 4, al[g][0], al[g][1], al[g][2], al[g][3], bh2, bh3);
                }
            }
        }
    }
    __syncthreads();

    float* stage = (float*)bp;
    int grp = lane >> 2, tg = lane & 3;
#pragma unroll
    for (int g = 0; g < 2; g++) {
        int rA = 32 * w + 16 * g + grp;
#pragma unroll
        for (int np = 0; np < 4; np++) {
            float* a4 = acc[g * 4 + np];
#pragma unroll
            for (int t = 0; t < 2; t++) {
                int col = np * 16 + t * 8 + tg * 2;
                stage[rA * 68 + col] = a4[t * 4 + 0] + sPar[col];
                stage[rA * 68 + col + 1] = a4[t * 4 + 1] + sPar[col + 1];
                stage[(rA + 8) * 68 + col] = a4[t * 4 + 2] + sPar[col];
                stage[(rA + 8) * 68 + col + 1] = a4[t * 4 + 3] + sPar[col + 1];
            }
        }
    }
    __syncthreads();
    {
        int row = row0 + tid;
        if (row >= N_NODES) {
#pragma unroll
            for (int f4 = 0; f4 < 16; f4++)
                *(float4*)&stage[tid * 68 + f4 * 4] = make_float4(0.f, 0.f, 0.f, 0.f);
        }
    }
    __syncthreads();
#pragma unroll 4
    for (int it = 0; it < 16; it++) {
        int idx = tid + it * 256;
        int r = idx >> 4, f4 = idx & 15;
        int rw = row0 + r;
        if (rw < N_NODES)
            *(float4*)&Z[(size_t)rw * 64 + f4 * 4] = *(float4*)&stage[r * 68 + f4 * 4];
    }
    int c = tid & 63, q = tid >> 6;
    float sum = 0.f, sq = 0.f;
#pragma unroll 8
    for (int rr = 0; rr < 64; rr++) {
        float x = stage[(q * 64 + rr) * 68 + c];
        sum += x;
        sq += x * x;
    }
    atomicAdd(&stats[c], sum);
    atomicAdd(&stats[64 + c], sq);
}

// ----------------- merged stats + double-affine H writer (grid-synced, 391 blocks) -------
__global__ __launch_bounds__(256) void k_statwrite(
    const float* __restrict__ Z, const float* __restrict__ stA, const float* __restrict__ gA,
    const float* __restrict__ beA, const float* __restrict__ gB,
    const float* __restrict__ beB, float* __restrict__ H, int off,
    float* __restrict__ statsOut, float* __restrict__ scbuf, int* __restrict__ ctr) {
    __shared__ float aff[128];
    __shared__ float affB[128];
    __shared__ float sred[256 * 8];
    __shared__ int isLast;
    int tid = threadIdx.x;
    float inv = 1.0f / (float)N_NODES;
    if (tid < 64) {
        float m = stA[tid] * inv;
        float v = fmaxf(stA[64 + tid] * inv - m * m, 0.f);
        float s = gA[tid] * rsqrtf(v + BN_EPS);
        aff[tid] = s;
        aff[64 + tid] = beA[tid] - m * s;
    }
    __syncthreads();

    int row0 = blockIdx.x * 256;
    int rsub = tid >> 4, c0 = (tid & 15) * 4;
    float ps[4] = {}, pq[4] = {};
#pragma unroll 4
    for (int it = 0; it < 16; it++) {
        int r = row0 + it * 16 + rsub;
        if (r < N_NODES) {
            float4 z = *(const float4*)&Z[(size_t)r * 64 + c0];
            float a0 = fmaxf(z.x * aff[c0 + 0] + aff[64 + c0 + 0], 0.f);
            float a1 = fmaxf(z.y * aff[c0 + 1] + aff[64 + c0 + 1], 0.f);
            float a2 = fmaxf(z.z * aff[c0 + 2] + aff[64 + c0 + 2], 0.f);
            float a3 = fmaxf(z.w * aff[c0 + 3] + aff[64 + c0 + 3], 0.f);
            ps[0] += a0; pq[0] += a0 * a0;
            ps[1] += a1; pq[1] += a1 * a1;
            ps[2] += a2; pq[2] += a2 * a2;
            ps[3] += a3; pq[3] += a3 * a3;
        }
    }
    float* p = &sred[tid * 8];
#pragma unroll
    for (int j = 0; j < 4; j++) { p[j] = ps[j]; p[4 + j] = pq[j]; }
    __syncthreads();
    if (tid < 128) {
        int c = tid >> 1, m = tid & 1;
        float s = 0.f;
#pragma unroll
        for (int rg = 0; rg < 16; rg++) s += sred[(rg * 16 + (c >> 2)) * 8 + (c & 3) + 4 * m];
        atomicAdd(&statsOut[m * 64 + c], s);
    }
    __threadfence();
    __syncthreads();
    if (tid == 0) {
        int old = atomicAdd(ctr, 1);
        isLast = (old == (int)gridDim.x - 1);
    }
    __syncthreads();
    if (isLast) {
        if (tid < 64) {
            float m = statsOut[tid] * inv;
            float v = fmaxf(statsOut[64 + tid] * inv - m * m, 0.f);
            float s = gB[tid] * rsqrtf(v + BN_EPS);
            scbuf[tid] = s;
            scbuf[64 + tid] = beB[tid] - m * s;
        }
        __threadfence();
        __syncthreads();
        if (tid == 0) atomicExch(ctr, DONE_FLAG);
    } else {
        if (tid == 0) {
            while (atomicAdd(ctr, 0) != DONE_FLAG) __nanosleep(64);
        }
        __syncthreads();
    }
    __threadfence();
    if (tid < 64) {
        affB[tid] = scbuf[tid];
        affB[64 + tid] = scbuf[64 + tid];
    }
    __syncthreads();

#pragma unroll 4
    for (int it = 0; it < 16; it++) {
        int r = row0 + it * 16 + rsub;
        if (r < N_NODES) {
            float4 z = *(const float4*)&Z[(size_t)r * 64 + c0];
            float o[4] = {z.x, z.y, z.z, z.w};
#pragma unroll
            for (int j = 0; j < 4; j++) {
                o[j] = fmaxf(o[j] * aff[c0 + j] + aff[64 + c0 + j], 0.f);
                o[j] = fmaxf(o[j] * affB[c0 + j] + affB[64 + c0 + j], 0.f);
            }
            *(float4*)&H[(size_t)r * 256 + off + c0] = make_float4(o[0], o[1], o[2], o[3]);
        }
    }
}

// ----------------- H-slice writer (single affine; input layer) -----------------
__global__ void k_hwrite(const float* __restrict__ Z, const float* __restrict__ stA,
                         const float* __restrict__ gA, const float* __restrict__ beA,
                         float* __restrict__ H, int off) {
    __shared__ float aff[128];
    int tid = threadIdx.x;
    if (tid < 64) {
        float inv = 1.0f / (float)N_NODES;
        float m = stA[tid] * inv;
        float v = fmaxf(stA[64 + tid] * inv - m * m, 0.f);
        float s = gA[tid] * rsqrtf(v + BN_EPS);
        aff[tid] = s;
        aff[64 + tid] = beA[tid] - m * s;
    }
    __syncthreads();
    int r = blockIdx.x * 16 + (tid >> 4);
    int c0 = (tid & 15) * 4;
    float4 z = *(const float4*)&Z[(size_t)r * 64 + c0];
    float o[4] = {z.x, z.y, z.z, z.w};
#pragma unroll
    for (int j = 0; j < 4; j++) o[j] = fmaxf(o[j] * aff[c0 + j] + aff[64 + c0 + j], 0.f);
    *(float4*)&H[(size_t)r * 256 + off + c0] = make_float4(o[0], o[1], o[2], o[3]);
}

// ----------------- final readout -----------------
__global__ void k_out(const float* __restrict__ Z, const float* __restrict__ stA,
                      const float* __restrict__ gA, const float* __restrict__ beA,
                      const float* __restrict__ W2, const float* __restrict__ b2,
                      float* __restrict__ out) {
    __shared__ float Ws[640];
    __shared__ float bs[10];
    __shared__ float ss[64], tt[64];
    int tid = threadIdx.x;
    for (int i = tid; i < 640; i += 256) Ws[i] = W2[i];
    if (tid < 10) bs[tid] = b2[tid];
    if (tid < 64) {
        float inv = 1.0f / (float)N_NODES;
        float m = stA[tid] * inv;
        float v = fmaxf(stA[64 + tid] * inv - m * m, 0.f);
        float s = gA[tid] * rsqrtf(v + BN_EPS);
        ss[tid] = s;
        tt[tid] = beA[tid] - m * s;
    }
    __syncthreads();
    int row = blockIdx.x * 256 + tid;
    if (row >= N_NODES) return;
    float o[10];
#pragma unroll
    for (int j = 0; j < 10; j++) o[j] = bs[j];
    const float4* zp = (const float4*)(Z + (size_t)row * 64);
#pragma unroll
    for (int i = 0; i < 16; i++) {
        float4 v = zp[i];
        int c = i * 4;
        float a0 = fmaxf(v.x * ss[c + 0] + tt[c + 0], 0.f);
        float a1 = fmaxf(v.y * ss[c + 1] + tt[c + 1], 0.f);
        float a2 = fmaxf(v.z * ss[c + 2] + tt[c + 2], 0.f);
        float a3 = fmaxf(v.w * ss[c + 3] + tt[c + 3], 0.f);
#pragma unroll
        for (int j = 0; j < 10; j++)
            o[j] += a0 * Ws[(c + 0) * 10 + j] + a1 * Ws[(c + 1) * 10 + j] +
                    a2 * Ws[(c + 2) * 10 + j] + a3 * Ws[(c + 3) * 10 + j];
    }
#pragma unroll
    for (int j = 0; j < 10; j++) out[(size_t)row * 10 + j] = o[j];
}

// ============================ host ============================
extern "C" void kernel_launch(void* const* d_in, const int* in_sizes, int n_in, void* d_out,
                              int out_size) {
    const float* x = (const float*)d_in[0];
    const int* ei = (const int*)d_in[1];
    const float* W_in = (const float*)d_in[2];
    const float* b_in = (const float*)d_in[3];
    const float* g_in = (const float*)d_in[4];
    const float* be_in = (const float*)d_in[5];
    const float* eps = (const float*)d_in[6];
    const float* W1 = (const float*)d_in[7];
    const float* b1 = (const float*)d_in[8];
    const float* g1 = (const float*)d_in[9];
    const float* be1 = (const float*)d_in[10];
    const float* W2 = (const float*)d_in[11];
    const float* b2 = (const float*)d_in[12];
    const float* g2 = (const float*)d_in[13];
    const float* be2 = (const float*)d_in[14];
    const float* g_post = (const float*)d_in[15];
    const float* be_post = (const float*)d_in[16];
    const float* W_out1 = (const float*)d_in[17];
    const float* b_out1 = (const float*)d_in[18];
    const float* g_out = (const float*)d_in[19];
    const float* be_out = (const float*)d_in[20];
    const float* W_out2 = (const float*)d_in[21];
    const float* b_out2 = (const float*)d_in[22];
    float* out = (float*)d_out;

    float *H, *T1, *T2, *AG, *ST, *SC;
    __nv_bfloat16 *Whi, *Wlo;
    int *cnt, *excl, *rowptr, *cursor, *srcs, *bsum, *sync;
    cudaGetSymbolAddress((void**)&H, g_H);
    cudaGetSymbolAddress((void**)&T1, g_T1);
    cudaGetSymbolAddress((void**)&T2, g_T2);
    cudaGetSymbolAddress((void**)&AG, g_AG);
    cudaGetSymbolAddress((void**)&ST, g_stats);
    cudaGetSymbolAddress((void**)&SC, g_scale);
    cudaGetSymbolAddress((void**)&Whi, g_Whi);
    cudaGetSymbolAddress((void**)&Wlo, g_Wlo);
    cudaGetSymbolAddress((void**)&cnt, g_cnt);
    cudaGetSymbolAddress((void**)&excl, g_excl);
    cudaGetSymbolAddress((void**)&rowptr, g_rowptr);
    cudaGetSymbolAddress((void**)&cursor, g_cursor);
    cudaGetSymbolAddress((void**)&srcs, g_srcs);
    cudaGetSymbolAddress((void**)&bsum, g_bsum);
    cudaGetSymbolAddress((void**)&sync, g_sync);

    cudaFuncSetAttribute(k_gemm_mma, cudaFuncAttributeMaxDynamicSharedMemorySize, DYN_SMEM);

    const int P_GRID = N_PAD / 256;              // 391
    const int EDGE_GRID = N_EDGES / 256;         // 6250
    const int NODE16_GRID = N_NODES * 16 / 256;  // 6250
    const int HW_GRID = N_NODES / 16;            // 6250

    // 1: init   2: hist   3: scan1+blockscan
    k_init<<<400, 256>>>(ST, cnt, T1, T2, AG, H, sync, W_in, W1, W2, W_out1, Whi, Wlo);
    k_hist<<<EDGE_GRID, 256>>>(ei, cnt);
    k_scan1m<<<CSR_GRID, SCAN_B>>>(cnt, excl, bsum, &sync[0]);
    // 4: input projection GEMM (independent of CSR)
    k_gemm_mma<<<P_GRID, 256, DYN_SMEM>>>(x, 64, 1, 0, b_in, nullptr, nullptr, nullptr, T1,
                                          ST + 0 * 128, 1, Whi, Wlo);
    // 5: scan3   6: fill   7: h0 -> H slice 0
    k_scan3<<<CSR_GRID, SCAN_B>>>(excl, bsum, rowptr, cursor);
    k_fill<<<EDGE_GRID, 256>>>(ei, cursor, srcs);
    k_hwrite<<<HW_GRID, 256>>>(T1, ST + 0 * 128, g_in, be_in, H, 0);

    for (int i = 0; i < NLAYER; i++) {
        int off = i * 64;
        int s1 = 1 + 3 * i, s2 = 2 + 3 * i, s3 = 3 + 3 * i;
        k_aggr<<<NODE16_GRID, 256>>>(rowptr, srcs, H, off, eps, i, AG);
        k_gemm_mma<<<P_GRID, 256, DYN_SMEM>>>(AG, 64, 1, 1 + i, b1 + i * 64, nullptr, nullptr,
                                              nullptr, T1, ST + s1 * 128, 0, Whi, Wlo);
        k_gemm_mma<<<P_GRID, 256, DYN_SMEM>>>(T1, 64, 1, 4 + i, b2 + i * 64, ST + s1 * 128,
                                              g1 + i * 64, be1 + i * 64, T2, ST + s2 * 128, 0,
                                              Whi, Wlo);
        k_statwrite<<<RS_GRID, 256>>>(T2, ST + s2 * 128, g2 + i * 64, be2 + i * 64,
                                      g_post + i * 64, be_post + i * 64, H, off + 64,
                                      ST + s3 * 128, SC + i * 128, &sync[4 + i]);
    }

    // readout (K=256)
    k_gemm_mma<<<P_GRID, 256, DYN_SMEM>>>(H, 256, 4, 7, b_out1, nullptr, nullptr, nullptr, T1,
                                          ST + 10 * 128, 0, Whi, Wlo);
    k_out<<<RS_GRID, 256>>>(T1, ST + 10 * 128, g_out, be_out, W_out2, b_out2, out);

    (void)in_sizes; (void)n_in; (void)out_size;
}

// round 17
// speedup vs baseline: 1.5028x; 1.0407x over previous
#include <cuda_runtime.h>
#include <cuda_bf16.h>
#include <cstdint>

#define N_NODES 100000
#define N_PAD 100096          // 391 * 256
#define N_EDGES 1600000
#define NLAYER 3
#define BN_EPS 1e-5f
#define SCAN_B 1024
#define CSR_GRID 98
#define RS_GRID 391
#define DONE_FLAG (-12345)

// -------- scratch (static device globals; allocation-free) --------
__device__ float g_H[(size_t)N_PAD * 256];
__device__ float g_T1[(size_t)N_PAD * 64];
__device__ float g_T2[(size_t)N_PAD * 64];
__device__ float g_AG[(size_t)N_PAD * 64];
__device__ float g_stats[11 * 128];
__device__ float g_scale[NLAYER * 128];
__device__ int g_sync[16];
__device__ __nv_bfloat16 g_Whi[11 * 4096];
__device__ __nv_bfloat16 g_Wlo[11 * 4096];
__device__ int g_cnt[N_NODES];
__device__ int g_excl[N_NODES];
__device__ int g_rowptr[N_NODES + 1];
__device__ int g_cursor[N_NODES];
__device__ int g_srcs[N_EDGES];
__device__ int g_bsum[CSR_GRID];

__device__ __forceinline__ uint32_t s2u(const void* p) {
    uint32_t a;
    asm("{ .reg .u64 t; cvta.to.shared.u64 t, %1; cvt.u32.u64 %0, t; }" : "=r"(a) : "l"(p));
    return a;
}
static __device__ __forceinline__ uint32_t swz(uint32_t off) { return off ^ ((off >> 3) & 0x70); }

#define LDSM_X4(r0, r1, r2, r3, addr)                                                          \
    asm volatile("ldmatrix.sync.aligned.m8n8.x4.shared.b16 {%0,%1,%2,%3}, [%4];"               \
                 : "=r"(r0), "=r"(r1), "=r"(r2), "=r"(r3)                                      \
                 : "r"(addr))
#define MMA(dst, a0, a1, a2, a3, b0, b1)                                                       \
    asm volatile(                                                                              \
        "mma.sync.aligned.m16n8k16.row.col.f32.bf16.bf16.f32 "                                 \
        "{%0,%1,%2,%3},{%4,%5,%6,%7},{%8,%9},{%0,%1,%2,%3};"                                   \
        : "+f"((dst)[0]), "+f"((dst)[1]), "+f"((dst)[2]), "+f"((dst)[3])                       \
        : "r"(a0), "r"(a1), "r"(a2), "r"(a3), "r"(b0), "r"(b1))

// ----------------- init: zero scratch + sync counters + weight transpose/split ----------
__global__ void k_init(float* stats, int* cnt, float* T1, float* T2, float* AG, float* H,
                       int* sync, const float* __restrict__ W_in, const float* __restrict__ W1,
                       const float* __restrict__ W2, const float* __restrict__ W_out1,
                       __nv_bfloat16* __restrict__ hi, __nv_bfloat16* __restrict__ lo) {
    int i = blockIdx.x * 256 + threadIdx.x;
    if (i < 11 * 128) stats[i] = 0.f;
    if (i < 16) sync[i] = 0;
    if (i < N_NODES) cnt[i] = 0;
    if (i < (N_PAD - N_NODES) * 64) {
        T1[(size_t)N_NODES * 64 + i] = 0.f;
        T2[(size_t)N_NODES * 64 + i] = 0.f;
        AG[(size_t)N_NODES * 64 + i] = 0.f;
    }
    if (i < (N_PAD - N_NODES) * 256) H[(size_t)N_NODES * 256 + i] = 0.f;
    if (i < 11 * 4096) {
        int slot = i >> 12, within = i & 4095;
        int n = within >> 6, k = within & 63;
        float v;
        if (slot == 0) v = W_in[k * 64 + n];
        else if (slot <= 3) v = W1[(slot - 1) * 4096 + k * 64 + n];
        else if (slot <= 6) v = W2[(slot - 4) * 4096 + k * 64 + n];
        else v = W_out1[((slot - 7) * 64 + k) * 64 + n];
        __nv_bfloat16 h = __float2bfloat16(v);
        hi[i] = h;
        lo[i] = __float2bfloat16(v - __bfloat162float(h));
    }
}

// ----------------- CSR build -----------------
__global__ void k_hist(const int* __restrict__ ei, int* __restrict__ cnt) {
    int e = blockIdx.x * 256 + threadIdx.x;
    atomicAdd(&cnt[ei[N_EDGES + e]], 1);
}
__global__ __launch_bounds__(SCAN_B) void k_scan1m(const int* __restrict__ cnt,
                                                   int* __restrict__ excl,
                                                   int* __restrict__ bsum,
                                                   int* __restrict__ ctr) {
    __shared__ int sm[SCAN_B];
    __shared__ int isLast;
    int tid = threadIdx.x;
    int i = blockIdx.x * SCAN_B + tid;
    int v = (i < N_NODES) ? cnt[i] : 0;
    sm[tid] = v;
    __syncthreads();
    for (int ofs = 1; ofs < SCAN_B; ofs <<= 1) {
        int t = (tid >= ofs) ? sm[tid - ofs] : 0;
        __syncthreads();
        sm[tid] += t;
        __syncthreads();
    }
    if (i < N_NODES) excl[i] = sm[tid] - v;
    if (tid == SCAN_B - 1) bsum[blockIdx.x] = sm[tid];
    __threadfence();
    __syncthreads();
    if (tid == 0) {
        int old = atomicAdd(ctr, 1);
        isLast = (old == CSR_GRID - 1);
    }
    __syncthreads();
    if (!isLast) return;
    int bv = (tid < CSR_GRID) ? bsum[tid] : 0;
    sm[tid] = bv;
    __syncthreads();
    for (int ofs = 1; ofs < 128; ofs <<= 1) {
        int t = (tid >= ofs && tid < 128) ? sm[tid - ofs] : 0;
        __syncthreads();
        if (tid < 128) sm[tid] += t;
        __syncthreads();
    }
    if (tid < CSR_GRID) bsum[tid] = sm[tid] - bv;
}
__global__ void k_scan3(const int* __restrict__ excl, const int* __restrict__ bsum,
                        int* __restrict__ rowptr, int* __restrict__ cursor) {
    int i = blockIdx.x * SCAN_B + threadIdx.x;
    if (i < N_NODES) {
        int r = excl[i] + bsum[blockIdx.x];
        rowptr[i] = r;
        cursor[i] = r;
    }
    if (i == 0) rowptr[N_NODES] = N_EDGES;
}
__global__ void k_fill(const int* __restrict__ ei, int* __restrict__ cursor,
                       int* __restrict__ srcs) {
    int e = blockIdx.x * 256 + threadIdx.x;
    int pos = atomicAdd(&cursor[ei[N_EDGES + e]], 1);
    srcs[pos] = ei[e];
}

// ----------------- CSR aggregation (max-parallel, 4-wide unrolled gather) -----------------
__global__ void k_aggr(const int* __restrict__ rowptr, const int* __restrict__ srcs,
                       const float* __restrict__ H, int off, const float* __restrict__ eps,
                       int li, float* __restrict__ AG) {
    int g = blockIdx.x * 256 + threadIdx.x;
    int node = g >> 4, lane = g & 15;
    float e = 1.f + eps[li];
    float4 self = *(const float4*)&H[(size_t)node * 256 + off + lane * 4];
    float4 a0 = make_float4(e * self.x, e * self.y, e * self.z, e * self.w);
    float4 a1 = make_float4(0.f, 0.f, 0.f, 0.f);
    int beg = rowptr[node], end = rowptr[node + 1];
    int j = beg;
    for (; j + 4 <= end; j += 4) {
        int s0 = __ldg(&srcs[j]);
        int s1 = __ldg(&srcs[j + 1]);
        int s2 = __ldg(&srcs[j + 2]);
        int s3 = __ldg(&srcs[j + 3]);
        float4 v0 = *(const float4*)&H[(size_t)s0 * 256 + off + lane * 4];
        float4 v1 = *(const float4*)&H[(size_t)s1 * 256 + off + lane * 4];
        float4 v2 = *(const float4*)&H[(size_t)s2 * 256 + off + lane * 4];
        float4 v3 = *(const float4*)&H[(size_t)s3 * 256 + off + lane * 4];
        a0.x += v0.x; a0.y += v0.y; a0.z += v0.z; a0.w += v0.w;
        a1.x += v1.x; a1.y += v1.y; a1.z += v1.z; a1.w += v1.w;
        a0.x += v2.x; a0.y += v2.y; a0.z += v2.z; a0.w += v2.w;
        a1.x += v3.x; a1.y += v3.y; a1.z += v3.z; a1.w += v3.w;
    }
    for (; j < end; j++) {
        int s0 = __ldg(&srcs[j]);
        float4 v0 = *(const float4*)&H[(size_t)s0 * 256 + off + lane * 4];
        a0.x += v0.x; a0.y += v0.y; a0.z += v0.z; a0.w += v0.w;
    }
    a0.x += a1.x; a0.y += a1.y; a0.z += a1.z; a0.w += a1.w;
    *(float4*)&AG[(size_t)node * 64 + lane * 4] = a0;
}

// ================= HMMA GEMM, 256 threads, 256-ROW tile (m32n64 per warp) =================
// smem: A_hi[0,32K) A_lo[32K,64K) B_hi[64K,72K) B_lo[72K,80K); epilogue stage reuses [0,69632).
#define DYN_SMEM 83968
__global__ __launch_bounds__(256) void k_gemm_mma(
    const float* __restrict__ A, int lda, int ktiles, int wslot,
    const float* __restrict__ bias, const float* __restrict__ statsPrev,
    const float* __restrict__ gPrev, const float* __restrict__ bePrev, float* __restrict__ Z,
    float* __restrict__ stats, int guardA, const __nv_bfloat16* __restrict__ Whi,
    const __nv_bfloat16* __restrict__ Wlo) {
    extern __shared__ __align__(16) char dsm[];
    __shared__ float sPar[192];
    int tid = threadIdx.x;
    uint32_t raw = s2u(dsm);
    uint32_t base0 = (raw + 1023) & ~1023u;
    char* bp = dsm + (base0 - raw);

    if (tid < 64) {
        sPar[tid] = bias[tid];
        if (statsPrev) {
            float inv = 1.0f / (float)N_NODES;
            float m = statsPrev[tid] * inv;
            float v = fmaxf(statsPrev[64 + tid] * inv - m * m, 0.f);
            float s = gPrev[tid] * rsqrtf(v + BN_EPS);
            sPar[64 + tid] = s;
            sPar[128 + tid] = bePrev[tid] - m * s;
        }
    }
    int row0 = blockIdx.x * 256;
    int w = tid >> 5, lane = tid & 31;

    uint32_t aRB[2], aX[2];
#pragma unroll
    for (int g = 0; g < 2; g++) {
        int arow = 32 * w + 16 * g + (lane & 7) + (lane & 8);
        aRB[g] = base0 + (uint32_t)arow * 128;
        aX[g] = (uint32_t)(arow & 7) << 4;
    }
    uint32_t aColSel = ((lane >> 4) & 1) * 16;
    int browBase = (lane & 7) + ((lane >> 4) & 1) * 8;
    uint32_t bXor = (uint32_t)(browBase & 7) << 4;
    uint32_t bColSel = ((lane >> 3) & 1) * 16;

    float acc[8][8];
#pragma unroll
    for (int i = 0; i < 8; i++)
#pragma unroll
        for (int j = 0; j < 8; j++) acc[i][j] = 0.f;

    for (int kt = 0; kt < ktiles; kt++) {
        __syncthreads();
#pragma unroll 4
        for (int it = 0; it < 16; it++) {
            int idx = tid + it * 256;
            int r = idx >> 4, f4 = idx & 15;
            int row = row0 + r;
            float4 v = make_float4(0.f, 0.f, 0.f, 0.f);
            if (!guardA || row < N_NODES)
                v = *(const float4*)&A[(size_t)row * lda + kt * 64 + f4 * 4];
            if (statsPrev) {
                int c = f4 * 4;
                v.x = fmaxf(v.x * sPar[64 + c] + sPar[128 + c], 0.f);
                v.y = fmaxf(v.y * sPar[65 + c] + sPar[129 + c], 0.f);
                v.z = fmaxf(v.z * sPar[66 + c] + sPar[130 + c], 0.f);
                v.w = fmaxf(v.w * sPar[67 + c] + sPar[131 + c], 0.f);
            }
            __nv_bfloat162 h0 = __float22bfloat162_rn(make_float2(v.x, v.y));
            __nv_bfloat162 h1 = __float22bfloat162_rn(make_float2(v.z, v.w));
            float2 r0 = __bfloat1622float2(h0);
            float2 r1 = __bfloat1622float2(h1);
            __nv_bfloat162 l0 = __float22bfloat162_rn(make_float2(v.x - r0.x, v.y - r0.y));
            __nv_bfloat162 l1 = __float22bfloat162_rn(make_float2(v.z - r1.x, v.w - r1.y));
            uint32_t sw = swz((uint32_t)r * 128 + (uint32_t)f4 * 8);
            *(uint2*)(bp + sw) = make_uint2(*(uint32_t*)&h0, *(uint32_t*)&h1);
            *(uint2*)(bp + 32768 + sw) = make_uint2(*(uint32_t*)&l0, *(uint32_t*)&l1);
        }
        const __nv_bfloat16* wh = Whi + (size_t)(wslot + kt) * 4096;
        const __nv_bfloat16* wl = Wlo + (size_t)(wslot + kt) * 4096;
#pragma unroll
        for (int it = 0; it < 2; it++) {
            int idx = tid + it * 256;
            int n = idx >> 3, f8 = idx & 7;
            uint32_t sw = swz((uint32_t)n * 128 + (uint32_t)f8 * 16);
            *(uint4*)(bp + 65536 + sw) = *(const uint4*)&wh[n * 64 + f8 * 8];
            *(uint4*)(bp + 73728 + sw) = *(const uint4*)&wl[n * 64 + f8 * 8];
        }
        __syncthreads();

#pragma unroll
        for (int kc = 0; kc < 4; kc++) {
            uint32_t ac = (aColSel + (uint32_t)kc * 32);
            uint32_t ah[2][4], al[2][4];
#pragma unroll
            for (int g = 0; g < 2; g++) {
                LDSM_X4(ah[g][0], ah[g][1], ah[g][2], ah[g][3], aRB[g] + (ac ^ aX[g]));
                LDSM_X4(al[g][0], al[g][1], al[g][2], al[g][3], aRB[g] + 32768 + (ac ^ aX[g]));
            }
#pragma unroll
            for (int np = 0; np < 4; np++) {
                uint32_t boff = (uint32_t)(browBase + np * 16) * 128 +
                                (((uint32_t)kc * 32 + bColSel) ^ bXor);
                uint32_t bh0, bh1, bh2, bh3, bl0, bl1, bl2, bl3;
                LDSM_X4(bh0, bh1, bh2, bh3, base0 + 65536 + boff);
                LDSM_X4(bl0, bl1, bl2, bl3, base0 + 73728 + boff);
#pragma unroll
                for (int g = 0; g < 2; g++) {
                    float* a4 = acc[g * 4 + np];
                    MMA(a4, ah[g][0], ah[g][1], ah[g][2], ah[g][3], bh0, bh1);
                    MMA(a4, ah[g][0], ah[g][1], ah[g][2], ah[g][3], bl0, bl1);
                    MMA(a4, al[g][0], al[g][1], al[g][2], al[g][3], bh0, bh1);
                    MMA(a4 + 4, ah[g][0], ah[g][1], ah[g][2], ah[g][3], bh2, bh3);
                    MMA(a4 + 4, ah[g][0], ah[g][1], ah[g][2], ah[g][3], bl2, bl3);
                    MMA(a4 + 4, al[g][0], al[g][1], al[g][2], al[g][3], bh2, bh3);
                }
            }
        }
    }
    __syncthreads();

    float* stage = (float*)bp;
    int grp = lane >> 2, tg = lane & 3;
#pragma unroll
    for (int g = 0; g < 2; g++) {
        int rA = 32 * w + 16 * g + grp;
#pragma unroll
        for (int np = 0; np < 4; np++) {
            float* a4 = acc[g * 4 + np];
#pragma unroll
            for (int t = 0; t < 2; t++) {
                int col = np * 16 + t * 8 + tg * 2;
                stage[rA * 68 + col] = a4[t * 4 + 0] + sPar[col];
                stage[rA * 68 + col + 1] = a4[t * 4 + 1] + sPar[col + 1];
                stage[(rA + 8) * 68 + col] = a4[t * 4 + 2] + sPar[col];
                stage[(rA + 8) * 68 + col + 1] = a4[t * 4 + 3] + sPar[col + 1];
            }
        }
    }
    __syncthreads();
    {
        int row = row0 + tid;
        if (row >= N_NODES) {
#pragma unroll
            for (int f4 = 0; f4 < 16; f4++)
                *(float4*)&stage[tid * 68 + f4 * 4] = make_float4(0.f, 0.f, 0.f, 0.f);
        }
    }
    __syncthreads();
#pragma unroll 4
    for (int it = 0; it < 16; it++) {
        int idx = tid + it * 256;
        int r = idx >> 4, f4 = idx & 15;
        int rw = row0 + r;
        if (rw < N_NODES)
            *(float4*)&Z[(size_t)rw * 64 + f4 * 4] = *(float4*)&stage[r * 68 + f4 * 4];
    }
    int c = tid & 63, q = tid >> 6;
    float sum = 0.f, sq = 0.f;
#pragma unroll 8
    for (int rr = 0; rr < 64; rr++) {
        float x = stage[(q * 64 + rr) * 68 + c];
        sum += x;
        sq += x * x;
    }
    atomicAdd(&stats[c], sum);
    atomicAdd(&stats[64 + c], sq);
}

// ----------------- merged stats + double-affine H writer (grid-synced, 391 blocks) -------
__global__ __launch_bounds__(256) void k_statwrite(
    const float* __restrict__ Z, const float* __restrict__ stA, const float* __restrict__ gA,
    const float* __restrict__ beA, const float* __restrict__ gB,
    const float* __restrict__ beB, float* __restrict__ H, int off,
    float* __restrict__ statsOut, float* __restrict__ scbuf, int* __restrict__ ctr) {
    __shared__ float aff[128];
    __shared__ float affB[128];
    __shared__ float sred[256 * 8];
    __shared__ int isLast;
    int tid = threadIdx.x;
    float inv = 1.0f / (float)N_NODES;
    if (tid < 64) {
        float m = stA[tid] * inv;
        float v = fmaxf(stA[64 + tid] * inv - m * m, 0.f);
        float s = gA[tid] * rsqrtf(v + BN_EPS);
        aff[tid] = s;
        aff[64 + tid] = beA[tid] - m * s;
    }
    __syncthreads();

    int row0 = blockIdx.x * 256;
    int rsub = tid >> 4, c0 = (tid & 15) * 4;
    float ps[4] = {}, pq[4] = {};
#pragma unroll 4
    for (int it = 0; it < 16; it++) {
        int r = row0 + it * 16 + rsub;
        if (r < N_NODES) {
            float4 z = *(const float4*)&Z[(size_t)r * 64 + c0];
            float a0 = fmaxf(z.x * aff[c0 + 0] + aff[64 + c0 + 0], 0.f);
            float a1 = fmaxf(z.y * aff[c0 + 1] + aff[64 + c0 + 1], 0.f);
            float a2 = fmaxf(z.z * aff[c0 + 2] + aff[64 + c0 + 2], 0.f);
            float a3 = fmaxf(z.w * aff[c0 + 3] + aff[64 + c0 + 3], 0.f);
            ps[0] += a0; pq[0] += a0 * a0;
            ps[1] += a1; pq[1] += a1 * a1;
            ps[2] += a2; pq[2] += a2 * a2;
            ps[3] += a3; pq[3] += a3 * a3;
        }
    }
    float* p = &sred[tid * 8];
#pragma unroll
    for (int j = 0; j < 4; j++) { p[j] = ps[j]; p[4 + j] = pq[j]; }
    __syncthreads();
    if (tid < 128) {
        int c = tid >> 1, m = tid & 1;
        float s = 0.f;
#pragma unroll
        for (int rg = 0; rg < 16; rg++) s += sred[(rg * 16 + (c >> 2)) * 8 + (c & 3) + 4 * m];
        atomicAdd(&statsOut[m * 64 + c], s);
    }
    __threadfence();
    __syncthreads();
    if (tid == 0) {
        int old = atomicAdd(ctr, 1);
        isLast = (old == (int)gridDim.x - 1);
    }
    __syncthreads();
    if (isLast) {
        if (tid < 64) {
            float m = statsOut[tid] * inv;
            float v = fmaxf(statsOut[64 + tid] * inv - m * m, 0.f);
            float s = gB[tid] * rsqrtf(v + BN_EPS);
            scbuf[tid] = s;
            scbuf[64 + tid] = beB[tid] - m * s;
        }
        __threadfence();
        __syncthreads();
        if (tid == 0) atomicExch(ctr, DONE_FLAG);
    } else {
        if (tid == 0) {
            while (atomicAdd(ctr, 0) != DONE_FLAG) __nanosleep(64);
        }
        __syncthreads();
    }
    __threadfence();
    if (tid < 64) {
        affB[tid] = scbuf[tid];
        affB[64 + tid] = scbuf[64 + tid];
    }
    __syncthreads();

#pragma unroll 4
    for (int it = 0; it < 16; it++) {
        int r = row0 + it * 16 + rsub;
        if (r < N_NODES) {
            float4 z = *(const float4*)&Z[(size_t)r * 64 + c0];
            float o[4] = {z.x, z.y, z.z, z.w};
#pragma unroll
            for (int j = 0; j < 4; j++) {
                o[j] = fmaxf(o[j] * aff[c0 + j] + aff[64 + c0 + j], 0.f);
                o[j] = fmaxf(o[j] * affB[c0 + j] + affB[64 + c0 + j], 0.f);
            }
            *(float4*)&H[(size_t)r * 256 + off + c0] = make_float4(o[0], o[1], o[2], o[3]);
        }
    }
}

// ----------------- H-slice writer (single affine; input layer) -----------------
__global__ void k_hwrite(const float* __restrict__ Z, const float* __restrict__ stA,
                         const float* __restrict__ gA, const float* __restrict__ beA,
                         float* __restrict__ H, int off) {
    __shared__ float aff[128];
    int tid = threadIdx.x;
    if (tid < 64) {
        float inv = 1.0f / (float)N_NODES;
        float m = stA[tid] * inv;
        float v = fmaxf(stA[64 + tid] * inv - m * m, 0.f);
        float s = gA[tid] * rsqrtf(v + BN_EPS);
        aff[tid] = s;
        aff[64 + tid] = beA[tid] - m * s;
    }
    __syncthreads();
    int r = blockIdx.x * 16 + (tid >> 4);
    int c0 = (tid & 15) * 4;
    float4 z = *(const float4*)&Z[(size_t)r * 64 + c0];
    float o[4] = {z.x, z.y, z.z, z.w};
#pragma unroll
    for (int j = 0; j < 4; j++) o[j] = fmaxf(o[j] * aff[c0 + j] + aff[64 + c0 + j], 0.f);
    *(float4*)&H[(size_t)r * 256 + off + c0] = make_float4(o[0], o[1], o[2], o[3]);
}

// ----------------- final readout -----------------
__global__ void k_out(const float* __restrict__ Z, const float* __restrict__ stA,
                      const float* __restrict__ gA, const float* __restrict__ beA,
                      const float* __restrict__ W2, const float* __restrict__ b2,
                      float* __restrict__ out) {
    __shared__ float Ws[640];
    __shared__ float bs[10];
    __shared__ float ss[64], tt[64];
    int tid = threadIdx.x;
    for (int i = tid; i < 640; i += 256) Ws[i] = W2[i];
    if (tid < 10) bs[tid] = b2[tid];
    if (tid < 64) {
        float inv = 1.0f / (float)N_NODES;
        float m = stA[tid] * inv;
        float v = fmaxf(stA[64 + tid] * inv - m * m, 0.f);
        float s = gA[tid] * rsqrtf(v + BN_EPS);
        ss[tid] = s;
        tt[tid] = beA[tid] - m * s;
    }
    __syncthreads();
    int row = blockIdx.x * 256 + tid;
    if (row >= N_NODES) return;
    float o[10];
#pragma unroll
    for (int j = 0; j < 10; j++) o[j] = bs[j];
    const float4* zp = (const float4*)(Z + (size_t)row * 64);
#pragma unroll
    for (int i = 0; i < 16; i++) {
        float4 v = zp[i];
        int c = i * 4;
        float a0 = fmaxf(v.x * ss[c + 0] + tt[c + 0], 0.f);
        float a1 = fmaxf(v.y * ss[c + 1] + tt[c + 1], 0.f);
        float a2 = fmaxf(v.z * ss[c + 2] + tt[c + 2], 0.f);
        float a3 = fmaxf(v.w * ss[c + 3] + tt[c + 3], 0.f);
#pragma unroll
        for (int j = 0; j < 10; j++)
            o[j] += a0 * Ws[(c + 0) * 10 + j] + a1 * Ws[(c + 1) * 10 + j] +
                    a2 * Ws[(c + 2) * 10 + j] + a3 * Ws[(c + 3) * 10 + j];
    }
#pragma unroll
    for (int j = 0; j < 10; j++) out[(size_t)row * 10 + j] = o[j];
}

// ============================ host ============================
extern "C" void kernel_launch(void* const* d_in, const int* in_sizes, int n_in, void* d_out,
                              int out_size) {
    const float* x = (const float*)d_in[0];
    const int* ei = (const int*)d_in[1];
    const float* W_in = (const float*)d_in[2];
    const float* b_in = (const float*)d_in[3];
    const float* g_in = (const float*)d_in[4];
    const float* be_in = (const float*)d_in[5];
    const float* eps = (const float*)d_in[6];
    const float* W1 = (const float*)d_in[7];
    const float* b1 = (const float*)d_in[8];
    const float* g1 = (const float*)d_in[9];
    const float* be1 = (const float*)d_in[10];
    const float* W2 = (const float*)d_in[11];
    const float* b2 = (const float*)d_in[12];
    const float* g2 = (const float*)d_in[13];
    const float* be2 = (const float*)d_in[14];
    const float* g_post = (const float*)d_in[15];
    const float* be_post = (const float*)d_in[16];
    const float* W_out1 = (const float*)d_in[17];
    const float* b_out1 = (const float*)d_in[18];
    const float* g_out = (const float*)d_in[19];
    const float* be_out = (const float*)d_in[20];
    const float* W_out2 = (const float*)d_in[21];
    const float* b_out2 = (const float*)d_in[22];
    float* out = (float*)d_out;

    float *H, *T1, *T2, *AG, *ST, *SC;
    __nv_bfloat16 *Whi, *Wlo;
    int *cnt, *excl, *rowptr, *cursor, *srcs, *bsum, *sync;
    cudaGetSymbolAddress((void**)&H, g_H);
    cudaGetSymbolAddress((void**)&T1, g_T1);
    cudaGetSymbolAddress((void**)&T2, g_T2);
    cudaGetSymbolAddress((void**)&AG, g_AG);
    cudaGetSymbolAddress((void**)&ST, g_stats);
    cudaGetSymbolAddress((void**)&SC, g_scale);
    cudaGetSymbolAddress((void**)&Whi, g_Whi);
    cudaGetSymbolAddress((void**)&Wlo, g_Wlo);
    cudaGetSymbolAddress((void**)&cnt, g_cnt);
    cudaGetSymbolAddress((void**)&excl, g_excl);
    cudaGetSymbolAddress((void**)&rowptr, g_rowptr);
    cudaGetSymbolAddress((void**)&cursor, g_cursor);
    cudaGetSymbolAddress((void**)&srcs, g_srcs);
    cudaGetSymbolAddress((void**)&bsum, g_bsum);
    cudaGetSymbolAddress((void**)&sync, g_sync);

    cudaFuncSetAttribute(k_gemm_mma, cudaFuncAttributeMaxDynamicSharedMemorySize, DYN_SMEM);

    // persistent side stream + fork/join events (created once; not device memory)
    static cudaStream_t s2 = nullptr;
    static cudaEvent_t evFork = nullptr, evJoin = nullptr;
    if (s2 == nullptr) {
        cudaStreamCreateWithFlags(&s2, cudaStreamNonBlocking);
        cudaEventCreateWithFlags(&evFork, cudaEventDisableTiming);
        cudaEventCreateWithFlags(&evJoin, cudaEventDisableTiming);
    }

    const int P_GRID = N_PAD / 256;              // 391
    const int EDGE_GRID = N_EDGES / 256;         // 6250
    const int NODE16_GRID = N_NODES * 16 / 256;  // 6250
    const int HW_GRID = N_NODES / 16;            // 6250

    // init (both branches depend on it)
    k_init<<<400, 256>>>(ST, cnt, T1, T2, AG, H, sync, W_in, W1, W2, W_out1, Whi, Wlo);

    // ---- fork: CSR build (s2) || input GEMM + h0 write (main) ----
    cudaEventRecord(evFork, 0);
    cudaStreamWaitEvent(s2, evFork, 0);

    k_hist<<<EDGE_GRID, 256, 0, s2>>>(ei, cnt);
    k_scan1m<<<CSR_GRID, SCAN_B, 0, s2>>>(cnt, excl, bsum, &sync[0]);
    k_scan3<<<CSR_GRID, SCAN_B, 0, s2>>>(excl, bsum, rowptr, cursor);
    k_fill<<<EDGE_GRID, 256, 0, s2>>>(ei, cursor, srcs);

    k_gemm_mma<<<P_GRID, 256, DYN_SMEM>>>(x, 64, 1, 0, b_in, nullptr, nullptr, nullptr, T1,
                                          ST + 0 * 128, 1, Whi, Wlo);
    k_hwrite<<<HW_GRID, 256>>>(T1, ST + 0 * 128, g_in, be_in, H, 0);

    // ---- join ----
    cudaEventRecord(evJoin, s2);
    cudaStreamWaitEvent(0, evJoin, 0);

    for (int i = 0; i < NLAYER; i++) {
        int off = i * 64;
        int s1 = 1 + 3 * i, sB = 2 + 3 * i, s3 = 3 + 3 * i;
        k_aggr<<<NODE16_GRID, 256>>>(rowptr, srcs, H, off, eps, i, AG);
        k_gemm_mma<<<P_GRID, 256, DYN_SMEM>>>(AG, 64, 1, 1 + i, b1 + i * 64, nullptr, nullptr,
                                              nullptr, T1, ST + s1 * 128, 0, Whi, Wlo);
        k_gemm_mma<<<P_GRID, 256, DYN_SMEM>>>(T1, 64, 1, 4 + i, b2 + i * 64, ST + s1 * 128,
                                              g1 + i * 64, be1 + i * 64, T2, ST + sB * 128, 0,
                                              Whi, Wlo);
        k_statwrite<<<RS_GRID, 256>>>(T2, ST + sB * 128, g2 + i * 64, be2 + i * 64,
                                      g_post + i * 64, be_post + i * 64, H, off + 64,
                                      ST + s3 * 128, SC + i * 128, &sync[4 + i]);
    }

    // readout (K=256)
    k_gemm_mma<<<P_GRID, 256, DYN_SMEM>>>(H, 256, 4, 7, b_out1, nullptr, nullptr, nullptr, T1,
                                          ST + 10 * 128, 0, Whi, Wlo);
    k_out<<<RS_GRID, 256>>>(T1, ST + 10 * 128, g_out, be_out, W_out2, b_out2, out);

    (void)in_sizes; (void)n_in; (void)out_size;
}